// round 1
// baseline (speedup 1.0000x reference)
#include <cuda_runtime.h>
#include <math.h>

#define NTOK 4096
#define HDIM 4096
#define FDIM 14336
#define NEXP 8
#define NR   8
#define LSCALE 2.0f

// Scratch (allocation-free rule: __device__ globals)
__device__ float g_h1[(size_t)NTOK * FDIM];   // x@w1, then silu(h1)*h3
__device__ float g_h3[(size_t)NTOK * FDIM];   // x@w3
__device__ float g_c[NTOK * NEXP * NR];       // sparse LoRA coefficients [N,64]

// ---------------------------------------------------------------------------
// Kernel 1: router logits + softmax top-2 + renorm + LoRA-A projection coeffs
// One block per token, 128 threads.
// ---------------------------------------------------------------------------
__global__ void __launch_bounds__(128) router_lora_kernel(
    const float* __restrict__ x,        // [N, H]
    const float* __restrict__ router_w, // [E, H]
    const float* __restrict__ lora_A,   // [E, H, R]
    float* __restrict__ logits_out)     // [N, E] or nullptr
{
    int n = blockIdx.x;
    __shared__ float xs[HDIM];
    __shared__ float logits[NEXP];
    __shared__ int   sel[2];
    __shared__ float rws[2];

    const float* xr = x + (size_t)n * HDIM;
    for (int i = threadIdx.x; i < HDIM / 4; i += blockDim.x)
        ((float4*)xs)[i] = ((const float4*)xr)[i];
    __syncthreads();

    int wid = threadIdx.x >> 5, lane = threadIdx.x & 31;
    // 4 warps x 2 experts each
    for (int e = wid; e < NEXP; e += 4) {
        const float* wr = router_w + (size_t)e * HDIM;
        float s = 0.f;
        for (int h = lane; h < HDIM; h += 32) s += xs[h] * wr[h];
        #pragma unroll
        for (int o = 16; o; o >>= 1) s += __shfl_down_sync(0xffffffffu, s, o);
        if (lane == 0) {
            logits[e] = s;
            if (logits_out) logits_out[(size_t)n * NEXP + e] = s;
        }
    }
    __syncthreads();

    if (threadIdx.x == 0) {
        float m = -1e30f;
        for (int e = 0; e < NEXP; e++) m = fmaxf(m, logits[e]);
        float p[NEXP], tot = 0.f;
        for (int e = 0; e < NEXP; e++) { p[e] = expf(logits[e] - m); tot += p[e]; }
        (void)tot; // top-2 + renorm makes the global denominator cancel
        int i0 = 0;
        for (int e = 1; e < NEXP; e++) if (p[e] > p[i0]) i0 = e;
        int i1 = -1;
        for (int e = 0; e < NEXP; e++) {
            if (e == i0) continue;
            if (i1 < 0 || p[e] > p[i1]) i1 = e;
        }
        float s2 = p[i0] + p[i1];
        sel[0] = i0; sel[1] = i1;
        rws[0] = p[i0] / s2; rws[1] = p[i1] / s2;
    }
    // zero the 64-wide coefficient row
    if (threadIdx.x < NEXP * NR) g_c[n * NEXP * NR + threadIdx.x] = 0.f;
    __syncthreads();

    // 16 dots (2 selected experts x 8 ranks), 8 threads per dot
    int p  = threadIdx.x >> 3;   // 0..15
    int l8 = threadIdx.x & 7;    // 0..7
    int k  = p >> 3;             // which of the 2 selected experts
    int r  = p & 7;              // rank
    int e  = sel[k];
    const float* A = lora_A + (size_t)e * HDIM * NR + r;
    float s = 0.f;
    for (int h = l8; h < HDIM; h += 8) s += xs[h] * A[(size_t)h * NR];
    s += __shfl_down_sync(0xffffffffu, s, 4);
    s += __shfl_down_sync(0xffffffffu, s, 2);
    s += __shfl_down_sync(0xffffffffu, s, 1);
    if (l8 == 0) g_c[n * NEXP * NR + e * NR + r] = rws[k] * LSCALE * s;
}

// ---------------------------------------------------------------------------
// Classic fp32 SGEMM: C[M,N] (+)= A[M,K] @ B[K,N], 128x128 block, 8x8/thread
// ---------------------------------------------------------------------------
__global__ void __launch_bounds__(256) sgemm128_kernel(
    const float* __restrict__ A, const float* __restrict__ B,
    float* __restrict__ C, int M, int N, int K, int accumulate)
{
    __shared__ float As[8][128];
    __shared__ float Bs[8][128];

    int tid = threadIdx.x;
    int m0 = blockIdx.y * 128, n0 = blockIdx.x * 128;

    int aRow = tid >> 1, aCol = (tid & 1) * 4;      // A tile: 128 rows x 8 k
    int bRow = tid >> 5, bCol = (tid & 31) * 4;     // B tile: 8 k x 128 cols

    const float* Aptr = A + (size_t)(m0 + aRow) * K + aCol;
    const float* Bptr = B + (size_t)bRow * N + n0 + bCol;

    int ty = tid >> 4, tx = tid & 15;

    float acc[8][8];
    #pragma unroll
    for (int i = 0; i < 8; i++)
        #pragma unroll
        for (int j = 0; j < 8; j++) acc[i][j] = 0.f;

    for (int k0 = 0; k0 < K; k0 += 8) {
        float4 av = *(const float4*)Aptr; Aptr += 8;
        float4 bv = *(const float4*)Bptr; Bptr += (size_t)8 * N;

        As[aCol + 0][aRow] = av.x;
        As[aCol + 1][aRow] = av.y;
        As[aCol + 2][aRow] = av.z;
        As[aCol + 3][aRow] = av.w;
        *(float4*)&Bs[bRow][bCol] = bv;
        __syncthreads();

        #pragma unroll
        for (int kk = 0; kk < 8; kk++) {
            float a[8], b[8];
            *(float4*)(a)     = *(const float4*)&As[kk][ty * 8];
            *(float4*)(a + 4) = *(const float4*)&As[kk][ty * 8 + 4];
            *(float4*)(b)     = *(const float4*)&Bs[kk][tx * 8];
            *(float4*)(b + 4) = *(const float4*)&Bs[kk][tx * 8 + 4];
            #pragma unroll
            for (int i = 0; i < 8; i++)
                #pragma unroll
                for (int j = 0; j < 8; j++)
                    acc[i][j] = fmaf(a[i], b[j], acc[i][j]);
        }
        __syncthreads();
    }

    #pragma unroll
    for (int i = 0; i < 8; i++) {
        float* Cr = C + (size_t)(m0 + ty * 8 + i) * N + n0 + tx * 8;
        if (accumulate) {
            float4 c0 = *(float4*)Cr;
            float4 c1 = *(float4*)(Cr + 4);
            c0.x += acc[i][0]; c0.y += acc[i][1]; c0.z += acc[i][2]; c0.w += acc[i][3];
            c1.x += acc[i][4]; c1.y += acc[i][5]; c1.z += acc[i][6]; c1.w += acc[i][7];
            *(float4*)Cr       = c0;
            *(float4*)(Cr + 4) = c1;
        } else {
            float4 c0 = make_float4(acc[i][0], acc[i][1], acc[i][2], acc[i][3]);
            float4 c1 = make_float4(acc[i][4], acc[i][5], acc[i][6], acc[i][7]);
            *(float4*)Cr       = c0;
            *(float4*)(Cr + 4) = c1;
        }
    }
}

// ---------------------------------------------------------------------------
// Elementwise: g_h1 = silu(g_h1) * g_h3
// ---------------------------------------------------------------------------
__global__ void silu_mul_kernel()
{
    size_t n4 = (size_t)NTOK * FDIM / 4;
    size_t stride = (size_t)gridDim.x * blockDim.x;
    for (size_t i = (size_t)blockIdx.x * blockDim.x + threadIdx.x; i < n4; i += stride) {
        float4 a = ((float4*)g_h1)[i];
        float4 b = ((float4*)g_h3)[i];
        a.x = a.x / (1.f + expf(-a.x)) * b.x;
        a.y = a.y / (1.f + expf(-a.y)) * b.y;
        a.z = a.z / (1.f + expf(-a.z)) * b.z;
        a.w = a.w / (1.f + expf(-a.w)) * b.w;
        ((float4*)g_h1)[i] = a;
    }
}

// ---------------------------------------------------------------------------
extern "C" void kernel_launch(void* const* d_in, const int* in_sizes, int n_in,
                              void* d_out, int out_size)
{
    const float* x        = (const float*)d_in[0]; // [N, H]
    const float* router_w = (const float*)d_in[1]; // [E, H]
    const float* w1       = (const float*)d_in[2]; // [H, F]
    const float* w2       = (const float*)d_in[3]; // [F, H]
    const float* w3       = (const float*)d_in[4]; // [H, F]
    const float* lora_A   = (const float*)d_in[5]; // [E, H, R]
    const float* lora_B   = (const float*)d_in[6]; // [E, R, H] == [64, H]
    float* out = (float*)d_out;

    static float *h1 = nullptr, *h3 = nullptr, *cc = nullptr;
    if (!h1) {
        cudaGetSymbolAddress((void**)&h1, g_h1);
        cudaGetSymbolAddress((void**)&h3, g_h3);
        cudaGetSymbolAddress((void**)&cc, g_c);
    }

    // router_logits is the reference's second output; write only if d_out covers it
    float* logits_out = nullptr;
    if ((size_t)out_size >= (size_t)NTOK * HDIM + (size_t)NTOK * NEXP)
        logits_out = out + (size_t)NTOK * HDIM;

    // 1) router + LoRA coefficients
    router_lora_kernel<<<NTOK, 128>>>(x, router_w, lora_A, logits_out);

    // 2) LoRA output = c[N,64] @ lora_B[64,H]  (initializes out; beta=0)
    {
        dim3 grid(HDIM / 128, NTOK / 128);
        sgemm128_kernel<<<grid, 256>>>(cc, lora_B, out, NTOK, HDIM, NEXP * NR, 0);
    }

    // 3) h1 = x @ w1 ; 4) h3 = x @ w3
    {
        dim3 grid(FDIM / 128, NTOK / 128);
        sgemm128_kernel<<<grid, 256>>>(x, w1, h1, NTOK, FDIM, HDIM, 0);
        sgemm128_kernel<<<grid, 256>>>(x, w3, h3, NTOK, FDIM, HDIM, 0);
    }

    // 5) h1 = silu(h1) * h3
    silu_mul_kernel<<<4096, 256>>>();

    // 6) out += h1 @ w2
    {
        dim3 grid(HDIM / 128, NTOK / 128);
        sgemm128_kernel<<<grid, 256>>>(h1, w2, out, NTOK, HDIM, FDIM, 1);
    }
}

// round 3
// speedup vs baseline: 3.4925x; 3.4925x over previous
#include <cuda_runtime.h>
#include <cuda_bf16.h>
#include <cstdint>
#include <math.h>

#define NTOK 4096
#define HDIM 4096
#define FDIM 14336
#define NEXP 8
#define NR   8
#define LSCALE 2.0f

// ---------------------------------------------------------------------------
// Scratch (__device__ globals; allocation-free rule)
// ---------------------------------------------------------------------------
__device__ __nv_bfloat16 g_xhi[(size_t)NTOK * HDIM];
__device__ __nv_bfloat16 g_xlo[(size_t)NTOK * HDIM];
__device__ __nv_bfloat16 g_b1hi[(size_t)FDIM * HDIM];  // w1^T [F,H]
__device__ __nv_bfloat16 g_b1lo[(size_t)FDIM * HDIM];
__device__ __nv_bfloat16 g_b3hi[(size_t)FDIM * HDIM];  // w3^T
__device__ __nv_bfloat16 g_b3lo[(size_t)FDIM * HDIM];
__device__ __nv_bfloat16 g_b2hi[(size_t)HDIM * FDIM];  // w2^T [H,F]
__device__ __nv_bfloat16 g_b2lo[(size_t)HDIM * FDIM];
__device__ __nv_bfloat16 g_a2hi[(size_t)NTOK * FDIM];  // silu(h1)*h3 split
__device__ __nv_bfloat16 g_a2lo[(size_t)NTOK * FDIM];
__device__ float g_h1[(size_t)NTOK * FDIM];            // x@w1 gate (fp32)
__device__ float g_c[NTOK * NEXP * NR];                // LoRA coefficients

// ---------------------------------------------------------------------------
// Asm helpers (sm_80-level: cp.async / ldmatrix / mma.sync — legal on sm_103)
// ---------------------------------------------------------------------------
__device__ __forceinline__ uint32_t smem_u32(const void* p) {
    uint32_t a;
    asm("{ .reg .u64 t; cvta.to.shared.u64 t, %1; cvt.u32.u64 %0, t; }" : "=r"(a) : "l"(p));
    return a;
}

#define CP16(dst, src) \
    asm volatile("cp.async.cg.shared.global [%0], [%1], 16;" \
        :: "r"(dst), "l"(src))

#define CP_COMMIT() asm volatile("cp.async.commit_group;" ::: "memory")
#define CP_WAIT1()  asm volatile("cp.async.wait_group 1;" ::: "memory")

#define LDSM4(r0, r1, r2, r3, a) \
    asm volatile("ldmatrix.sync.aligned.m8n8.x4.shared.b16 {%0,%1,%2,%3}, [%4];" \
        : "=r"(r0), "=r"(r1), "=r"(r2), "=r"(r3) : "r"(a))

#define MMA_BF16(c, a0, a1, a2, a3, b0, b1) \
    asm volatile("mma.sync.aligned.m16n8k16.row.col.f32.bf16.bf16.f32 " \
        "{%0,%1,%2,%3}, {%4,%5,%6,%7}, {%8,%9}, {%0,%1,%2,%3};" \
        : "+f"((c)[0]), "+f"((c)[1]), "+f"((c)[2]), "+f"((c)[3]) \
        : "r"(a0), "r"(a1), "r"(a2), "r"(a3), "r"(b0), "r"(b1))

// ---------------------------------------------------------------------------
// Conversion kernels
// ---------------------------------------------------------------------------
__global__ void __launch_bounds__(256) split_x_kernel(const float* __restrict__ x) {
    size_t n = (size_t)NTOK * HDIM;
    size_t stride = (size_t)gridDim.x * blockDim.x * 4;
    for (size_t i = ((size_t)blockIdx.x * blockDim.x + threadIdx.x) * 4; i < n; i += stride) {
        float4 v = *(const float4*)(x + i);
        float vv[4] = {v.x, v.y, v.z, v.w};
        #pragma unroll
        for (int j = 0; j < 4; j++) {
            __nv_bfloat16 h = __float2bfloat16_rn(vv[j]);
            g_xhi[i + j] = h;
            g_xlo[i + j] = __float2bfloat16_rn(vv[j] - __bfloat162float(h));
        }
    }
}

// W [K,N] fp32  ->  hi/lo [N,K] bf16 (transpose + split)
__global__ void __launch_bounds__(256) transpose_split_kernel(
    const float* __restrict__ W, __nv_bfloat16* __restrict__ hi,
    __nv_bfloat16* __restrict__ lo, int K, int N)
{
    __shared__ float t[32][33];
    int n0 = blockIdx.x * 32, k0 = blockIdx.y * 32;
    int tx = threadIdx.x & 31, ty = threadIdx.x >> 5;   // 32 x 8
    #pragma unroll
    for (int j = 0; j < 4; j++)
        t[ty + 8 * j][tx] = W[(size_t)(k0 + ty + 8 * j) * N + n0 + tx];
    __syncthreads();
    #pragma unroll
    for (int j = 0; j < 4; j++) {
        int r = ty + 8 * j;
        float v = t[tx][r];
        size_t o = (size_t)(n0 + r) * K + k0 + tx;
        __nv_bfloat16 h = __float2bfloat16_rn(v);
        hi[o] = h;
        lo[o] = __float2bfloat16_rn(v - __bfloat162float(h));
    }
}

// ---------------------------------------------------------------------------
// Router + LoRA coefficients
// ---------------------------------------------------------------------------
__global__ void __launch_bounds__(128) router_lora_kernel(
    const float* __restrict__ x, const float* __restrict__ router_w,
    const float* __restrict__ lora_A, float* __restrict__ logits_out)
{
    int n = blockIdx.x;
    __shared__ float xs[HDIM];
    __shared__ float logits[NEXP];
    __shared__ int   sel[2];
    __shared__ float rws[2];

    const float* xr = x + (size_t)n * HDIM;
    for (int i = threadIdx.x; i < HDIM / 4; i += blockDim.x)
        ((float4*)xs)[i] = ((const float4*)xr)[i];
    __syncthreads();

    int wid = threadIdx.x >> 5, lane = threadIdx.x & 31;
    for (int e = wid; e < NEXP; e += 4) {
        const float* wr = router_w + (size_t)e * HDIM;
        float s = 0.f;
        for (int h = lane; h < HDIM; h += 32) s += xs[h] * wr[h];
        #pragma unroll
        for (int o = 16; o; o >>= 1) s += __shfl_down_sync(0xffffffffu, s, o);
        if (lane == 0) {
            logits[e] = s;
            if (logits_out) logits_out[(size_t)n * NEXP + e] = s;
        }
    }
    __syncthreads();

    if (threadIdx.x == 0) {
        float m = -1e30f;
        for (int e = 0; e < NEXP; e++) m = fmaxf(m, logits[e]);
        float p[NEXP];
        for (int e = 0; e < NEXP; e++) p[e] = expf(logits[e] - m);
        int i0 = 0;
        for (int e = 1; e < NEXP; e++) if (p[e] > p[i0]) i0 = e;
        int i1 = -1;
        for (int e = 0; e < NEXP; e++) {
            if (e == i0) continue;
            if (i1 < 0 || p[e] > p[i1]) i1 = e;
        }
        float s2 = p[i0] + p[i1];
        sel[0] = i0; sel[1] = i1;
        rws[0] = p[i0] / s2; rws[1] = p[i1] / s2;
    }
    if (threadIdx.x < NEXP * NR) g_c[n * NEXP * NR + threadIdx.x] = 0.f;
    __syncthreads();

    int p  = threadIdx.x >> 3;
    int l8 = threadIdx.x & 7;
    int k  = p >> 3;
    int r  = p & 7;
    int e  = sel[k];
    const float* A = lora_A + (size_t)e * HDIM * NR + r;
    float s = 0.f;
    for (int h = l8; h < HDIM; h += 8) s += xs[h] * A[(size_t)h * NR];
    s += __shfl_down_sync(0xffffffffu, s, 4);
    s += __shfl_down_sync(0xffffffffu, s, 2);
    s += __shfl_down_sync(0xffffffffu, s, 1);
    if (l8 == 0) g_c[n * NEXP * NR + e * NR + r] = rws[k] * LSCALE * s;
}

// ---------------------------------------------------------------------------
// Small fp32 SGEMM for LoRA (K=64), writes out with beta=0
// ---------------------------------------------------------------------------
__global__ void __launch_bounds__(256) sgemm128_kernel(
    const float* __restrict__ A, const float* __restrict__ B,
    float* __restrict__ C, int M, int N, int K)
{
    __shared__ float As[8][128];
    __shared__ float Bs[8][128];
    int tid = threadIdx.x;
    int m0 = blockIdx.y * 128, n0 = blockIdx.x * 128;
    int aRow = tid >> 1, aCol = (tid & 1) * 4;
    int bRow = tid >> 5, bCol = (tid & 31) * 4;
    const float* Aptr = A + (size_t)(m0 + aRow) * K + aCol;
    const float* Bptr = B + (size_t)bRow * N + n0 + bCol;
    int ty = tid >> 4, tx = tid & 15;

    float acc[8][8];
    #pragma unroll
    for (int i = 0; i < 8; i++)
        #pragma unroll
        for (int j = 0; j < 8; j++) acc[i][j] = 0.f;

    for (int k0 = 0; k0 < K; k0 += 8) {
        float4 av = *(const float4*)Aptr; Aptr += 8;
        float4 bv = *(const float4*)Bptr; Bptr += (size_t)8 * N;
        As[aCol + 0][aRow] = av.x; As[aCol + 1][aRow] = av.y;
        As[aCol + 2][aRow] = av.z; As[aCol + 3][aRow] = av.w;
        *(float4*)&Bs[bRow][bCol] = bv;
        __syncthreads();
        #pragma unroll
        for (int kk = 0; kk < 8; kk++) {
            float a[8], b[8];
            *(float4*)(a)     = *(const float4*)&As[kk][ty * 8];
            *(float4*)(a + 4) = *(const float4*)&As[kk][ty * 8 + 4];
            *(float4*)(b)     = *(const float4*)&Bs[kk][tx * 8];
            *(float4*)(b + 4) = *(const float4*)&Bs[kk][tx * 8 + 4];
            #pragma unroll
            for (int i = 0; i < 8; i++)
                #pragma unroll
                for (int j = 0; j < 8; j++)
                    acc[i][j] = fmaf(a[i], b[j], acc[i][j]);
        }
        __syncthreads();
    }
    #pragma unroll
    for (int i = 0; i < 8; i++) {
        float* Cr = C + (size_t)(m0 + ty * 8 + i) * N + n0 + tx * 8;
        *(float4*)Cr       = make_float4(acc[i][0], acc[i][1], acc[i][2], acc[i][3]);
        *(float4*)(Cr + 4) = make_float4(acc[i][4], acc[i][5], acc[i][6], acc[i][7]);
    }
}

// ---------------------------------------------------------------------------
// bf16x3 GEMM via mma.sync: D = Ahi*Bhi + Ahi*Blo + Alo*Bhi (fp32 accum)
// A [M,K] and B [N,K] both K-major bf16. CTA tile 128x128, BK=64, 3 stages.
// mode 0: C  = D
// mode 1: v  = silu(gate) * D ; split v into bf16 hi/lo -> oHi/oLo
// mode 2: C += D
// ---------------------------------------------------------------------------
#define STAGE_BYTES 65536
#define GEMM_SMEM   (3 * STAGE_BYTES)

__device__ __forceinline__ void issue_stage(
    uint32_t st, const __nv_bfloat16* Ah, const __nv_bfloat16* Al,
    const __nv_bfloat16* Bh, const __nv_bfloat16* Bl,
    int m0, int n0, int kpos, int K, int lr, int lkc)
{
    #pragma unroll
    for (int rr = 0; rr < 128; rr += 32) {
        int row = lr + rr;
        uint32_t so = row * 128 + ((lkc ^ (row & 7)) << 4);
        size_t ga = (size_t)(m0 + row) * K + kpos + lkc * 8;
        size_t gb = (size_t)(n0 + row) * K + kpos + lkc * 8;
        CP16(st + so,         Ah + ga);
        CP16(st + 16384 + so, Al + ga);
        CP16(st + 32768 + so, Bh + gb);
        CP16(st + 49152 + so, Bl + gb);
    }
    CP_COMMIT();
}

__global__ void __launch_bounds__(256, 1) gemm_bf16x3_kernel(
    const __nv_bfloat16* __restrict__ Ah, const __nv_bfloat16* __restrict__ Al,
    const __nv_bfloat16* __restrict__ Bh, const __nv_bfloat16* __restrict__ Bl,
    float* __restrict__ C, const float* __restrict__ gate,
    __nv_bfloat16* __restrict__ oHi, __nv_bfloat16* __restrict__ oLo,
    int K, int mode)
{
    extern __shared__ __align__(1024) char smem[];
    uint32_t sb = smem_u32(smem);
    int tid = threadIdx.x;
    int wid = tid >> 5, lane = tid & 31;
    int wm = wid >> 2, wn = wid & 3;          // 2 x 4 warps, warp tile 64m x 32n
    int m0 = blockIdx.y * 128, n0 = blockIdx.x * 128;
    int NT = K >> 6;

    int lr = tid >> 3, lkc = tid & 7;         // load map

    // ldmatrix address precompute
    int laneM  = lane & 15;
    int kHalfA = lane >> 4;
    int aSw    = laneM & 7;
    uint32_t rowOffA[4];
    #pragma unroll
    for (int tm = 0; tm < 4; tm++)
        rowOffA[tm] = (uint32_t)(wm * 64 + tm * 16 + laneM) * 128;
    int l7     = lane & 7;
    int kHalfB = (lane >> 3) & 1;
    uint32_t rowOffB[2];
    #pragma unroll
    for (int pr = 0; pr < 2; pr++)
        rowOffB[pr] = (uint32_t)(wn * 32 + pr * 16 + ((lane >> 4) & 1) * 8 + l7) * 128;

    float acc[4][4][4];
    #pragma unroll
    for (int i = 0; i < 4; i++)
        #pragma unroll
        for (int j = 0; j < 4; j++)
            #pragma unroll
            for (int q = 0; q < 4; q++) acc[i][j][q] = 0.f;

    issue_stage(sb,               Ah, Al, Bh, Bl, m0, n0, 0,  K, lr, lkc);
    issue_stage(sb + STAGE_BYTES, Ah, Al, Bh, Bl, m0, n0, 64, K, lr, lkc);

    for (int kt = 0; kt < NT; kt++) {
        CP_WAIT1();
        __syncthreads();
        if (kt + 2 < NT)
            issue_stage(sb + ((kt + 2) % 3) * STAGE_BYTES, Ah, Al, Bh, Bl,
                        m0, n0, (kt + 2) << 6, K, lr, lkc);
        else
            CP_COMMIT();  // keep committed-count = kt+2 so WAIT1 retires stage kt

        uint32_t st = sb + (kt % 3) * STAGE_BYTES;
        #pragma unroll
        for (int kk = 0; kk < 4; kk++) {
            uint32_t ah[4][4], al[4][4], bh[8], bl[8];
            uint32_t chA = (uint32_t)(((kk * 2 + kHalfA) ^ aSw) << 4);
            #pragma unroll
            for (int tm = 0; tm < 4; tm++) {
                LDSM4(ah[tm][0], ah[tm][1], ah[tm][2], ah[tm][3], st + rowOffA[tm] + chA);
                LDSM4(al[tm][0], al[tm][1], al[tm][2], al[tm][3], st + 16384 + rowOffA[tm] + chA);
            }
            uint32_t chB = (uint32_t)(((kk * 2 + kHalfB) ^ l7) << 4);
            LDSM4(bh[0], bh[1], bh[2], bh[3], st + 32768 + rowOffB[0] + chB);
            LDSM4(bh[4], bh[5], bh[6], bh[7], st + 32768 + rowOffB[1] + chB);
            LDSM4(bl[0], bl[1], bl[2], bl[3], st + 49152 + rowOffB[0] + chB);
            LDSM4(bl[4], bl[5], bl[6], bl[7], st + 49152 + rowOffB[1] + chB);
            #pragma unroll
            for (int tm = 0; tm < 4; tm++)
                #pragma unroll
                for (int tn = 0; tn < 4; tn++) {
                    MMA_BF16(acc[tm][tn], ah[tm][0], ah[tm][1], ah[tm][2], ah[tm][3],
                             bh[2 * tn], bh[2 * tn + 1]);
                    MMA_BF16(acc[tm][tn], ah[tm][0], ah[tm][1], ah[tm][2], ah[tm][3],
                             bl[2 * tn], bl[2 * tn + 1]);
                    MMA_BF16(acc[tm][tn], al[tm][0], al[tm][1], al[tm][2], al[tm][3],
                             bh[2 * tn], bh[2 * tn + 1]);
                }
        }
    }

    // epilogue
    int g2 = lane >> 2, q2 = (lane & 3) * 2;
    size_t Nt = (size_t)gridDim.x * 128;
    #pragma unroll
    for (int tm = 0; tm < 4; tm++) {
        #pragma unroll
        for (int tn = 0; tn < 4; tn++) {
            int mg = m0 + wm * 64 + tm * 16 + g2;
            int cg = n0 + wn * 32 + tn * 8 + q2;
            size_t o0 = (size_t)mg * Nt + cg;
            size_t o1 = o0 + 8 * Nt;
            float* a = acc[tm][tn];
            if (mode == 0) {
                *(float2*)(C + o0) = make_float2(a[0], a[1]);
                *(float2*)(C + o1) = make_float2(a[2], a[3]);
            } else if (mode == 1) {
                float2 ga0 = *(const float2*)(gate + o0);
                float2 ga1 = *(const float2*)(gate + o1);
                float v0 = ga0.x / (1.f + __expf(-ga0.x)) * a[0];
                float v1 = ga0.y / (1.f + __expf(-ga0.y)) * a[1];
                float v2 = ga1.x / (1.f + __expf(-ga1.x)) * a[2];
                float v3 = ga1.y / (1.f + __expf(-ga1.y)) * a[3];
                __nv_bfloat16 h0 = __float2bfloat16_rn(v0);
                __nv_bfloat16 h1 = __float2bfloat16_rn(v1);
                __nv_bfloat16 h2 = __float2bfloat16_rn(v2);
                __nv_bfloat16 h3 = __float2bfloat16_rn(v3);
                __nv_bfloat162 hp0; hp0.x = h0; hp0.y = h1;
                __nv_bfloat162 hp1; hp1.x = h2; hp1.y = h3;
                *(__nv_bfloat162*)(oHi + o0) = hp0;
                *(__nv_bfloat162*)(oHi + o1) = hp1;
                __nv_bfloat162 lp0, lp1;
                lp0.x = __float2bfloat16_rn(v0 - __bfloat162float(h0));
                lp0.y = __float2bfloat16_rn(v1 - __bfloat162float(h1));
                lp1.x = __float2bfloat16_rn(v2 - __bfloat162float(h2));
                lp1.y = __float2bfloat16_rn(v3 - __bfloat162float(h3));
                *(__nv_bfloat162*)(oLo + o0) = lp0;
                *(__nv_bfloat162*)(oLo + o1) = lp1;
            } else {
                float2 c0 = *(const float2*)(C + o0);
                float2 c1 = *(const float2*)(C + o1);
                c0.x += a[0]; c0.y += a[1];
                c1.x += a[2]; c1.y += a[3];
                *(float2*)(C + o0) = c0;
                *(float2*)(C + o1) = c1;
            }
        }
    }
}

// ---------------------------------------------------------------------------
extern "C" void kernel_launch(void* const* d_in, const int* in_sizes, int n_in,
                              void* d_out, int out_size)
{
    const float* x        = (const float*)d_in[0];
    const float* router_w = (const float*)d_in[1];
    const float* w1       = (const float*)d_in[2];
    const float* w2       = (const float*)d_in[3];
    const float* w3       = (const float*)d_in[4];
    const float* lora_A   = (const float*)d_in[5];
    const float* lora_B   = (const float*)d_in[6];
    float* out = (float*)d_out;

    static bool init_done = false;
    static float *h1, *cc;
    static __nv_bfloat16 *xhi, *xlo, *b1hi, *b1lo, *b3hi, *b3lo, *b2hi, *b2lo, *a2hi, *a2lo;
    if (!init_done) {
        cudaGetSymbolAddress((void**)&h1,  g_h1);
        cudaGetSymbolAddress((void**)&cc,  g_c);
        cudaGetSymbolAddress((void**)&xhi, g_xhi);
        cudaGetSymbolAddress((void**)&xlo, g_xlo);
        cudaGetSymbolAddress((void**)&b1hi, g_b1hi);
        cudaGetSymbolAddress((void**)&b1lo, g_b1lo);
        cudaGetSymbolAddress((void**)&b3hi, g_b3hi);
        cudaGetSymbolAddress((void**)&b3lo, g_b3lo);
        cudaGetSymbolAddress((void**)&b2hi, g_b2hi);
        cudaGetSymbolAddress((void**)&b2lo, g_b2lo);
        cudaGetSymbolAddress((void**)&a2hi, g_a2hi);
        cudaGetSymbolAddress((void**)&a2lo, g_a2lo);
        cudaFuncSetAttribute(gemm_bf16x3_kernel,
                             cudaFuncAttributeMaxDynamicSharedMemorySize, GEMM_SMEM);
        init_done = true;
    }

    float* logits_out = nullptr;
    if ((size_t)out_size >= (size_t)NTOK * HDIM + (size_t)NTOK * NEXP)
        logits_out = out + (size_t)NTOK * HDIM;

    // conversions
    split_x_kernel<<<8192, 256>>>(x);
    transpose_split_kernel<<<dim3(FDIM / 32, HDIM / 32), 256>>>(w1, b1hi, b1lo, HDIM, FDIM);
    transpose_split_kernel<<<dim3(FDIM / 32, HDIM / 32), 256>>>(w3, b3hi, b3lo, HDIM, FDIM);
    transpose_split_kernel<<<dim3(HDIM / 32, FDIM / 32), 256>>>(w2, b2hi, b2lo, FDIM, HDIM);

    // router + LoRA coefficients; LoRA GEMM initializes out (beta=0)
    router_lora_kernel<<<NTOK, 128>>>(x, router_w, lora_A, logits_out);
    sgemm128_kernel<<<dim3(HDIM / 128, NTOK / 128), 256>>>(cc, lora_B, out, NTOK, HDIM, NEXP * NR);

    // GEMM1: h1 = x @ w1 (fp32 gate)
    gemm_bf16x3_kernel<<<dim3(FDIM / 128, NTOK / 128), 256, GEMM_SMEM>>>(
        xhi, xlo, b1hi, b1lo, h1, nullptr, nullptr, nullptr, HDIM, 0);

    // GEMM3 + fused silu-mul + split: a2 = split(silu(h1) * (x @ w3))
    gemm_bf16x3_kernel<<<dim3(FDIM / 128, NTOK / 128), 256, GEMM_SMEM>>>(
        xhi, xlo, b3hi, b3lo, nullptr, h1, a2hi, a2lo, HDIM, 1);

    // GEMM2: out += a2 @ w2
    gemm_bf16x3_kernel<<<dim3(HDIM / 128, NTOK / 128), 256, GEMM_SMEM>>>(
        a2hi, a2lo, b2hi, b2lo, out, nullptr, nullptr, nullptr, FDIM, 2);
}